// round 2
// baseline (speedup 1.0000x reference)
#include <cuda_runtime.h>
#include <cstdint>

// Problem shape (fixed per reference)
#define N_CASES 6
#define ROWS 16384
#define COLS 4096
#define SLAB_ELEMS (ROWS * COLS)            // 67,108,864 floats (fits int32)
#define SLAB_VEC4  (SLAB_ELEMS / 4)         // 16,777,216 float4 (fits int32)

__global__ __launch_bounds__(256, 6)
void select_copy_kernel(const float* __restrict__ x,
                        const float* __restrict__ fingerprints,
                        const float* __restrict__ cached_outputs,
                        float* __restrict__ out) {
    __shared__ int s_idx;

    // Every block independently computes the selected index (28 loads; L2-hot
    // after the first wave of blocks, negligible vs the 512 MiB stream).
    if (threadIdx.x == 0) {
        float p0 = x[0], p1 = x[1], p2 = x[2], p3 = x[3];
        int idx = 0;
        // Scan high->low so the LOWEST matching index survives (first match
        // wins). No match -> 0, matching reference argmax semantics.
        #pragma unroll
        for (int c = N_CASES - 1; c >= 0; --c) {
            const float* f = fingerprints + 4 * c;
            if (p0 == f[0] && p1 == f[1] && p2 == f[2] && p3 == f[3]) {
                idx = c;
            }
        }
        s_idx = idx;
    }
    __syncthreads();

    // 64-bit only for the base pointer; all loop indexing is 32-bit to keep
    // register pressure low (R1: long long indexing -> 96 regs -> 2 CTAs/SM).
    const float4* __restrict__ src =
        reinterpret_cast<const float4*>(cached_outputs) +
        (long long)s_idx * SLAB_VEC4;
    float4* __restrict__ dst = reinterpret_cast<float4*>(out);

    const int stride = gridDim.x * blockDim.x;          // 888*256 = 227,328
    int i = blockIdx.x * blockDim.x + threadIdx.x;

    // 4x unrolled grid-stride streaming copy: 4 independent 128-bit loads
    // front-batched per iteration, streaming cache hints both directions.
    const int end4 = SLAB_VEC4 - 3 * stride;
    for (; i < end4; i += 4 * stride) {
        float4 v0 = __ldcs(src + i);
        float4 v1 = __ldcs(src + i + stride);
        float4 v2 = __ldcs(src + i + 2 * stride);
        float4 v3 = __ldcs(src + i + 3 * stride);
        __stcs(dst + i,              v0);
        __stcs(dst + i + stride,     v1);
        __stcs(dst + i + 2 * stride, v2);
        __stcs(dst + i + 3 * stride, v3);
    }
    for (; i < SLAB_VEC4; i += stride) {
        __stcs(dst + i, __ldcs(src + i));
    }
}

extern "C" void kernel_launch(void* const* d_in, const int* in_sizes, int n_in,
                              void* d_out, int out_size) {
    const float* x              = (const float*)d_in[0];
    const float* fingerprints   = (const float*)d_in[1];
    const float* cached_outputs = (const float*)d_in[2];
    float* out = (float*)d_out;

    const int threads = 256;
    const int blocks  = 148 * 6;   // 6 resident CTAs/SM -> exactly one wave
    select_copy_kernel<<<blocks, threads>>>(x, fingerprints, cached_outputs, out);
}

// round 3
// speedup vs baseline: 1.0076x; 1.0076x over previous
#include <cuda_runtime.h>
#include <cstdint>

// Problem shape (fixed per reference)
#define N_CASES 6
#define ROWS 16384
#define COLS 4096
#define SLAB_ELEMS (ROWS * COLS)            // 67,108,864 floats (fits int32)
#define SLAB_VEC4  (SLAB_ELEMS / 4)         // 16,777,216 float4 (fits int32)

__global__ __launch_bounds__(256, 5)
void select_copy_kernel(const float* __restrict__ x,
                        const float* __restrict__ fingerprints,
                        const float* __restrict__ cached_outputs,
                        float* __restrict__ out) {
    __shared__ int s_idx;

    // Every block independently computes the selected index (28 loads; L2-hot
    // after the first blocks, negligible vs the 512 MiB stream).
    if (threadIdx.x == 0) {
        float p0 = x[0], p1 = x[1], p2 = x[2], p3 = x[3];
        int idx = 0;
        // Scan high->low so the LOWEST matching index survives (first match
        // wins). No match -> 0, matching reference argmax semantics.
        #pragma unroll
        for (int c = N_CASES - 1; c >= 0; --c) {
            const float* f = fingerprints + 4 * c;
            if (p0 == f[0] && p1 == f[1] && p2 == f[2] && p3 == f[3]) {
                idx = c;
            }
        }
        s_idx = idx;
    }
    __syncthreads();

    // 64-bit only for the base pointer; all loop indexing stays 32-bit.
    const float4* __restrict__ src =
        reinterpret_cast<const float4*>(cached_outputs) +
        (long long)s_idx * SLAB_VEC4;
    float4* __restrict__ dst = reinterpret_cast<float4*>(out);

    const int stride = gridDim.x * blockDim.x;          // 740*256 = 189,440
    int i = blockIdx.x * blockDim.x + threadIdx.x;

    // 8x front-batched streaming copy: 8 independent 128-bit loads in flight
    // per thread (320 outstanding LDG/SM at 5 CTAs/SM) before any store.
    const int end8 = SLAB_VEC4 - 7 * stride;
    for (; i < end8; i += 8 * stride) {
        float4 v0 = __ldcs(src + i);
        float4 v1 = __ldcs(src + i + stride);
        float4 v2 = __ldcs(src + i + 2 * stride);
        float4 v3 = __ldcs(src + i + 3 * stride);
        float4 v4 = __ldcs(src + i + 4 * stride);
        float4 v5 = __ldcs(src + i + 5 * stride);
        float4 v6 = __ldcs(src + i + 6 * stride);
        float4 v7 = __ldcs(src + i + 7 * stride);
        __stcs(dst + i,              v0);
        __stcs(dst + i + stride,     v1);
        __stcs(dst + i + 2 * stride, v2);
        __stcs(dst + i + 3 * stride, v3);
        __stcs(dst + i + 4 * stride, v4);
        __stcs(dst + i + 5 * stride, v5);
        __stcs(dst + i + 6 * stride, v6);
        __stcs(dst + i + 7 * stride, v7);
    }
    for (; i < SLAB_VEC4; i += stride) {
        __stcs(dst + i, __ldcs(src + i));
    }
}

extern "C" void kernel_launch(void* const* d_in, const int* in_sizes, int n_in,
                              void* d_out, int out_size) {
    const float* x              = (const float*)d_in[0];
    const float* fingerprints   = (const float*)d_in[1];
    const float* cached_outputs = (const float*)d_in[2];
    float* out = (float*)d_out;

    const int threads = 256;
    const int blocks  = 148 * 5;   // 5 resident CTAs/SM -> exactly one wave
    select_copy_kernel<<<blocks, threads>>>(x, fingerprints, cached_outputs, out);
}